// round 11
// baseline (speedup 1.0000x reference)
#include <cuda_runtime.h>

#define B  8
#define BH 4     // batches per half
#define D  512
#define T  8192
#define CS 16
#define TC 512   // T / CS
#define DH 64    // D / 8

// Scratch (no cudaMalloc allowed)
__device__ float g_pooled[B * D * TC];          // 8 MiB
__device__ float g_hpart[4][B * DH * TC];       // 1 MiB per split-K slice

// ---------------------------------------------------------------------------
// Kernel 1: per (b,d) row — chunk sums of 16, inclusive scan, divide by count.
// Operates on a half-batch slab (boff..boff+BH). x reads cached (we rely on
// the 64 MiB half-slab staying L2-resident until gate_scale reads it back).
// ---------------------------------------------------------------------------
__global__ void pool_kernel(const float* __restrict__ x, int boff) {
    int row = boff * D + blockIdx.x;           // b*D + d within half
    const float4* xr = reinterpret_cast<const float4*>(x) + (size_t)row * (T / 4);
    int j = threadIdx.x;

    __shared__ float csum[TC];
    __shared__ float wsum[16];

    float4 f0 = xr[j];
    float4 f1 = xr[j + 512];
    float4 f2 = xr[j + 1024];
    float4 f3 = xr[j + 1536];

    float s0 = (f0.x + f0.y) + (f0.z + f0.w);
    float s1 = (f1.x + f1.y) + (f1.z + f1.w);
    float s2 = (f2.x + f2.y) + (f2.z + f2.w);
    float s3 = (f3.x + f3.y) + (f3.z + f3.w);

    s0 += __shfl_xor_sync(0xffffffffu, s0, 1);
    s0 += __shfl_xor_sync(0xffffffffu, s0, 2);
    s1 += __shfl_xor_sync(0xffffffffu, s1, 1);
    s1 += __shfl_xor_sync(0xffffffffu, s1, 2);
    s2 += __shfl_xor_sync(0xffffffffu, s2, 1);
    s2 += __shfl_xor_sync(0xffffffffu, s2, 2);
    s3 += __shfl_xor_sync(0xffffffffu, s3, 1);
    s3 += __shfl_xor_sync(0xffffffffu, s3, 2);

    if ((j & 3) == 0) {
        int c = j >> 2;
        csum[c +   0] = s0;
        csum[c + 128] = s1;
        csum[c + 256] = s2;
        csum[c + 384] = s3;
    }
    __syncthreads();

    int lane = j & 31, warp = j >> 5;
    float v = csum[j];
    #pragma unroll
    for (int off = 1; off < 32; off <<= 1) {
        float n = __shfl_up_sync(0xffffffffu, v, off);
        if (lane >= off) v += n;
    }
    if (lane == 31) wsum[warp] = v;
    __syncthreads();
    if (warp == 0) {
        float w = (lane < 16) ? wsum[lane] : 0.f;
        #pragma unroll
        for (int off = 1; off < 16; off <<= 1) {
            float n = __shfl_up_sync(0xffffffffu, w, off);
            if (lane >= off) w += n;
        }
        if (lane < 16) wsum[lane] = w;
    }
    __syncthreads();

    float prefix = (warp > 0) ? wsum[warp - 1] : 0.f;
    float total  = v + prefix;
    g_pooled[(size_t)row * TC + j] = total / (float)(CS * (j + 1));
}

// ---------------------------------------------------------------------------
// Kernel 2a: GEMM1 split-K partials for a half-batch.
// grid (16 t-tiles, 4 k-slices, BH) = 256 CTAs, 256 threads.
// Each CTA: out 64o x 32t, K=128. Thread: 4o x 2t... keep R5/R9 proven tile:
// t-tile 32 -> thread 4o x 4t over 32t needs 8 tq groups; use 8x32 mapping.
// ---------------------------------------------------------------------------
__global__ void __launch_bounds__(256) gemm1_kernel(const float* __restrict__ w1,
                                                    int boff) {
    __shared__ __align__(16) float Ps[64 * 32];      // [d][t] 8 KiB
    __shared__ __align__(16) float Ws[64 * 65 + 4];  // [o][d] padded

    int tid = threadIdx.x;
    int t0 = blockIdx.x * 32;
    int k0 = blockIdx.y * 128;
    int b  = boff + blockIdx.z;
    int tq = tid & 7;           // t quad -> t = tq*4..tq*4+3
    int og = tid >> 3;          // 0..31  -> o = og*2, og*2+1

    float acc[2][4];
    acc[0][0] = acc[0][1] = acc[0][2] = acc[0][3] = 0.f;
    acc[1][0] = acc[1][1] = acc[1][2] = acc[1][3] = 0.f;

    for (int c = 0; c < 2; c++) {
        int kc = k0 + c * 64;
        #pragma unroll
        for (int i = tid; i < 64 * 8; i += 256) {
            int d = i >> 3, t4 = i & 7;
            *reinterpret_cast<float4*>(&Ps[d * 32 + t4 * 4]) =
                *reinterpret_cast<const float4*>(
                    &g_pooled[((size_t)(b * D) + kc + d) * TC + t0 + t4 * 4]);
        }
        #pragma unroll
        for (int i = tid; i < 64 * 64; i += 256) {
            int o = i >> 6, d = i & 63;
            Ws[o * 65 + d] = w1[o * D + kc + d];
        }
        __syncthreads();

        #pragma unroll 8
        for (int dd = 0; dd < 64; dd++) {
            float4 p = *reinterpret_cast<const float4*>(&Ps[dd * 32 + tq * 4]);
            float w0 = Ws[(og * 2 + 0) * 65 + dd];
            float w1v = Ws[(og * 2 + 1) * 65 + dd];
            acc[0][0] = fmaf(w0, p.x, acc[0][0]);
            acc[0][1] = fmaf(w0, p.y, acc[0][1]);
            acc[0][2] = fmaf(w0, p.z, acc[0][2]);
            acc[0][3] = fmaf(w0, p.w, acc[0][3]);
            acc[1][0] = fmaf(w1v, p.x, acc[1][0]);
            acc[1][1] = fmaf(w1v, p.y, acc[1][1]);
            acc[1][2] = fmaf(w1v, p.z, acc[1][2]);
            acc[1][3] = fmaf(w1v, p.w, acc[1][3]);
        }
        __syncthreads();
    }

    float* hp = g_hpart[blockIdx.y];
    #pragma unroll
    for (int o = 0; o < 2; o++) {
        float4 v = make_float4(acc[o][0], acc[o][1], acc[o][2], acc[o][3]);
        *reinterpret_cast<float4*>(
            &hp[((size_t)(b * DH) + og * 2 + o) * TC + t0 + tq * 4]) = v;
    }
}

// ---------------------------------------------------------------------------
// Kernel 2b (FUSED): gemm2 + sigmoid gate + out = gate * x for a half-batch.
// grid (16, 8, BH) = 512 CTAs, 256 threads, smem ~25 KiB.
// x reads cached (L2-resident half slab); out writes streaming (__stcs).
// ---------------------------------------------------------------------------
__global__ void __launch_bounds__(256) gate_scale_kernel(
        const float* __restrict__ w2,
        const float* __restrict__ b1,
        const float* __restrict__ b2,
        const float* __restrict__ x,
        float* __restrict__ out,
        int boff) {
    __shared__ __align__(16) float Hs[64 * 32];      // [k][t] then gate [o][t]
    __shared__ __align__(16) float Ws[64 * 65 + 4];  // [o][k] padded

    int tid = threadIdx.x;
    int t0 = blockIdx.x * 32;                 // pooled-chunk tile start
    int o0 = (7 - blockIdx.y) * 64;           // reversed d-tile (LRU match)
    int b  = boff + (BH - 1) - blockIdx.z;    // reversed batch within half
    int tq = tid & 7;                         // t quad: t = tq*4..+3
    int og = tid >> 3;                        // 0..31 -> o = og*2, og*2+1

    // ---- Phase A1: H = relu(sum hpart + b1), W2 ----
    #pragma unroll
    for (int i = tid; i < 64 * 8; i += 256) {
        int k = i >> 3, t4 = i & 7;
        size_t idx = ((size_t)(b * DH) + k) * TC + t0 + t4 * 4;
        float4 a0 = *reinterpret_cast<const float4*>(&g_hpart[0][idx]);
        float4 a1 = *reinterpret_cast<const float4*>(&g_hpart[1][idx]);
        float4 a2 = *reinterpret_cast<const float4*>(&g_hpart[2][idx]);
        float4 a3 = *reinterpret_cast<const float4*>(&g_hpart[3][idx]);
        float bb = b1[k];
        float4 hv;
        hv.x = fmaxf(a0.x + a1.x + a2.x + a3.x + bb, 0.f);
        hv.y = fmaxf(a0.y + a1.y + a2.y + a3.y + bb, 0.f);
        hv.z = fmaxf(a0.z + a1.z + a2.z + a3.z + bb, 0.f);
        hv.w = fmaxf(a0.w + a1.w + a2.w + a3.w + bb, 0.f);
        *reinterpret_cast<float4*>(&Hs[k * 32 + t4 * 4]) = hv;
    }
    #pragma unroll
    for (int i = tid; i < 64 * 64; i += 256) {
        int o = i >> 6, k = i & 63;
        Ws[o * 65 + k] = w2[(o0 + o) * DH + k];
    }
    __syncthreads();

    // ---- Phase A2: GEMM 64o x 32t, K=64; thread = 2o x 4t ----
    float acc[2][4];
    acc[0][0] = acc[0][1] = acc[0][2] = acc[0][3] = 0.f;
    acc[1][0] = acc[1][1] = acc[1][2] = acc[1][3] = 0.f;

    #pragma unroll 8
    for (int k = 0; k < 64; k++) {
        float4 h = *reinterpret_cast<const float4*>(&Hs[k * 32 + tq * 4]);
        float w0 = Ws[(og * 2 + 0) * 65 + k];
        float w1v = Ws[(og * 2 + 1) * 65 + k];
        acc[0][0] = fmaf(w0, h.x, acc[0][0]);
        acc[0][1] = fmaf(w0, h.y, acc[0][1]);
        acc[0][2] = fmaf(w0, h.z, acc[0][2]);
        acc[0][3] = fmaf(w0, h.w, acc[0][3]);
        acc[1][0] = fmaf(w1v, h.x, acc[1][0]);
        acc[1][1] = fmaf(w1v, h.y, acc[1][1]);
        acc[1][2] = fmaf(w1v, h.z, acc[1][2]);
        acc[1][3] = fmaf(w1v, h.w, acc[1][3]);
    }
    __syncthreads();   // Hs reads done; reuse as gate

    // ---- Phase A3: sigmoid -> gate tile [o_local][32 t] ----
    #pragma unroll
    for (int o = 0; o < 2; o++) {
        float bb = b2[o0 + og * 2 + o];
        float4 g;
        g.x = 1.f / (1.f + __expf(-(acc[0 + o][0] + bb)));
        g.y = 1.f / (1.f + __expf(-(acc[0 + o][1] + bb)));
        g.z = 1.f / (1.f + __expf(-(acc[0 + o][2] + bb)));
        g.w = 1.f / (1.f + __expf(-(acc[0 + o][3] + bb)));
        *reinterpret_cast<float4*>(&Hs[(og * 2 + o) * 32 + tq * 4]) = g;
    }
    __syncthreads();

    // ---- Phase B: out = gate * x over [64 d-rows][512 cols] ----
    int warp = tid >> 5, lane = tid & 31;
    int c0 = t0 * CS;

    #pragma unroll
    for (int r = 0; r < 8; r++) {
        int o_local = warp * 8 + r;
        size_t rowbase = ((size_t)(b * D) + o0 + o_local) * T + c0;
        const float4* xr = reinterpret_cast<const float4*>(x + rowbase);
        float4*       orp = reinterpret_cast<float4*>(out + rowbase);

        float4 xv[4];
        #pragma unroll
        for (int i = 0; i < 4; i++)
            xv[i] = xr[i * 32 + lane];        // expect L2 hit (half-slab resident)

        float gv[4];
        #pragma unroll
        for (int i = 0; i < 4; i++)
            gv[i] = Hs[o_local * 32 + ((i * 32 + lane) >> 2)];

        #pragma unroll
        for (int i = 0; i < 4; i++) {
            float4 ov = make_float4(xv[i].x * gv[i], xv[i].y * gv[i],
                                    xv[i].z * gv[i], xv[i].w * gv[i]);
            __stcs(&orp[i * 32 + lane], ov);
        }
    }
}

// ---------------------------------------------------------------------------
extern "C" void kernel_launch(void* const* d_in, const int* in_sizes, int n_in,
                              void* d_out, int out_size) {
    const float* x  = (const float*)d_in[0];
    const float* w1 = (const float*)d_in[1];
    const float* b1 = (const float*)d_in[2];
    const float* w2 = (const float*)d_in[3];
    const float* b2 = (const float*)d_in[4];
    float* out = (float*)d_out;

    for (int h = 0; h < 2; h++) {
        int boff = h * BH;
        pool_kernel<<<BH * D, 512>>>(x, boff);
        gemm1_kernel<<<dim3(16, 4, BH), 256>>>(w1, boff);
        gate_scale_kernel<<<dim3(16, 8, BH), 256>>>(w2, b1, b2, x, out, boff);
    }
}

// round 12
// speedup vs baseline: 1.3015x; 1.3015x over previous
#include <cuda_runtime.h>

#define B  8
#define D  512
#define T  8192
#define CS 16
#define TC 512   // T / CS
#define DH 64    // D / 8

// Scratch (no cudaMalloc allowed)
__device__ float g_pooled[B * D * TC];          // 8 MiB
__device__ float g_hpart[4][B * DH * TC];       // 1 MiB per split-K slice

// ---------------------------------------------------------------------------
// Kernel 1: per (b,d) row — chunk sums of 16, inclusive scan, divide by count.
// Coalesced block-stride float4 loads, lane-group-of-4 reduction, block scan.
// Measured 23.6 us (~74% DRAM, at the achievable ceiling).
// ---------------------------------------------------------------------------
__global__ void pool_kernel(const float* __restrict__ x) {
    int row = blockIdx.x;                      // b*D + d
    const float4* xr = reinterpret_cast<const float4*>(x) + (size_t)row * (T / 4);
    int j = threadIdx.x;

    __shared__ float csum[TC];
    __shared__ float wsum[16];

    float4 f0 = xr[j];
    float4 f1 = xr[j + 512];
    float4 f2 = xr[j + 1024];
    float4 f3 = xr[j + 1536];

    float s0 = (f0.x + f0.y) + (f0.z + f0.w);
    float s1 = (f1.x + f1.y) + (f1.z + f1.w);
    float s2 = (f2.x + f2.y) + (f2.z + f2.w);
    float s3 = (f3.x + f3.y) + (f3.z + f3.w);

    s0 += __shfl_xor_sync(0xffffffffu, s0, 1);
    s0 += __shfl_xor_sync(0xffffffffu, s0, 2);
    s1 += __shfl_xor_sync(0xffffffffu, s1, 1);
    s1 += __shfl_xor_sync(0xffffffffu, s1, 2);
    s2 += __shfl_xor_sync(0xffffffffu, s2, 1);
    s2 += __shfl_xor_sync(0xffffffffu, s2, 2);
    s3 += __shfl_xor_sync(0xffffffffu, s3, 1);
    s3 += __shfl_xor_sync(0xffffffffu, s3, 2);

    if ((j & 3) == 0) {
        int c = j >> 2;
        csum[c +   0] = s0;
        csum[c + 128] = s1;
        csum[c + 256] = s2;
        csum[c + 384] = s3;
    }
    __syncthreads();

    int lane = j & 31, warp = j >> 5;
    float v = csum[j];
    #pragma unroll
    for (int off = 1; off < 32; off <<= 1) {
        float n = __shfl_up_sync(0xffffffffu, v, off);
        if (lane >= off) v += n;
    }
    if (lane == 31) wsum[warp] = v;
    __syncthreads();
    if (warp == 0) {
        float w = (lane < 16) ? wsum[lane] : 0.f;
        #pragma unroll
        for (int off = 1; off < 16; off <<= 1) {
            float n = __shfl_up_sync(0xffffffffu, w, off);
            if (lane >= off) w += n;
        }
        if (lane < 16) wsum[lane] = w;
    }
    __syncthreads();

    float prefix = (warp > 0) ? wsum[warp - 1] : 0.f;
    float total  = v + prefix;
    g_pooled[(size_t)row * TC + j] = total / (float)(CS * (j + 1));
}

// ---------------------------------------------------------------------------
// Kernel 2a: GEMM1 split-K partials (R9's proven config, ~9 us).
// grid (8 t-tiles, 4 k-slices, B) = 256 CTAs, 256 threads.
// ---------------------------------------------------------------------------
__global__ void __launch_bounds__(256) gemm1_kernel(const float* __restrict__ w1) {
    __shared__ __align__(16) float Ps[64 * 64];      // [d][t] 16 KiB
    __shared__ __align__(16) float Ws[64 * 65 + 4];  // [o][d] padded

    int tid = threadIdx.x;
    int t0 = blockIdx.x * 64;
    int k0 = blockIdx.y * 128;
    int b  = blockIdx.z;
    int tq = tid & 15;          // t quad -> t = tq*4..tq*4+3
    int og = tid >> 4;          // 0..15  -> o = og*4..og*4+3

    float acc[4][4];
    #pragma unroll
    for (int o = 0; o < 4; o++)
        #pragma unroll
        for (int q = 0; q < 4; q++) acc[o][q] = 0.f;

    for (int c = 0; c < 2; c++) {
        int kc = k0 + c * 64;
        #pragma unroll
        for (int i = tid; i < 64 * 16; i += 256) {
            int d = i >> 4, t4 = i & 15;
            *reinterpret_cast<float4*>(&Ps[d * 64 + t4 * 4]) =
                *reinterpret_cast<const float4*>(
                    &g_pooled[((size_t)(b * D) + kc + d) * TC + t0 + t4 * 4]);
        }
        #pragma unroll
        for (int i = tid; i < 64 * 64; i += 256) {
            int o = i >> 6, d = i & 63;
            Ws[o * 65 + d] = w1[o * D + kc + d];
        }
        __syncthreads();

        #pragma unroll 8
        for (int dd = 0; dd < 64; dd++) {
            float4 p = *reinterpret_cast<const float4*>(&Ps[dd * 64 + tq * 4]);
            #pragma unroll
            for (int o = 0; o < 4; o++) {
                float w = Ws[(og * 4 + o) * 65 + dd];
                acc[o][0] = fmaf(w, p.x, acc[o][0]);
                acc[o][1] = fmaf(w, p.y, acc[o][1]);
                acc[o][2] = fmaf(w, p.z, acc[o][2]);
                acc[o][3] = fmaf(w, p.w, acc[o][3]);
            }
        }
        __syncthreads();
    }

    float* hp = g_hpart[blockIdx.y];
    #pragma unroll
    for (int o = 0; o < 4; o++) {
        float4 v = make_float4(acc[o][0], acc[o][1], acc[o][2], acc[o][3]);
        *reinterpret_cast<float4*>(
            &hp[((size_t)(b * DH) + og * 4 + o) * TC + t0 + tq * 4]) = v;
    }
}

// ---------------------------------------------------------------------------
// Kernel 2b (FUSED): gemm2 + sigmoid gate + out = gate * x.
// t-tile 16 chunks (256 cols): grid (32, 8, 8) = 2048 CTAs (~1.7 waves at
// 8 CTA/SM) so wave-2 fronts hide behind wave-1 streaming. smem ~21 KiB.
// y/z reversed for L2 LRU match; out via __stcs.
// ---------------------------------------------------------------------------
__global__ void __launch_bounds__(256) gate_scale_kernel(
        const float* __restrict__ w2,
        const float* __restrict__ b1,
        const float* __restrict__ b2,
        const float* __restrict__ x,
        float* __restrict__ out) {
    __shared__ __align__(16) float Hs[64 * 16];      // [k][t] then gate [o][t]
    __shared__ __align__(16) float Ws[64 * 65 + 4];  // [o][k] padded

    int tid = threadIdx.x;
    int t0 = blockIdx.x * 16;                 // pooled-chunk tile start
    int o0 = (7 - blockIdx.y) * 64;           // reversed d-tile
    int b  = (B - 1) - blockIdx.z;            // reversed batch
    int tq = tid & 3;                         // t quad: t = tq*4..+3
    int og = tid >> 2;                        // 0..63 -> one o row

    // ---- Phase A1: H = relu(sum hpart + b1)  (one float4 per thread) ----
    {
        int k = tid >> 2, t4 = tid & 3;
        size_t idx = ((size_t)(b * DH) + k) * TC + t0 + t4 * 4;
        float4 a0 = *reinterpret_cast<const float4*>(&g_hpart[0][idx]);
        float4 a1 = *reinterpret_cast<const float4*>(&g_hpart[1][idx]);
        float4 a2 = *reinterpret_cast<const float4*>(&g_hpart[2][idx]);
        float4 a3 = *reinterpret_cast<const float4*>(&g_hpart[3][idx]);
        float bb = b1[k];
        float4 hv;
        hv.x = fmaxf(a0.x + a1.x + a2.x + a3.x + bb, 0.f);
        hv.y = fmaxf(a0.y + a1.y + a2.y + a3.y + bb, 0.f);
        hv.z = fmaxf(a0.z + a1.z + a2.z + a3.z + bb, 0.f);
        hv.w = fmaxf(a0.w + a1.w + a2.w + a3.w + bb, 0.f);
        *reinterpret_cast<float4*>(&Hs[k * 16 + t4 * 4]) = hv;
    }
    #pragma unroll
    for (int i = tid; i < 64 * 64; i += 256) {
        int o = i >> 6, k = i & 63;
        Ws[o * 65 + k] = w2[(o0 + o) * DH + k];
    }
    __syncthreads();

    // ---- Phase A2: GEMM 64o x 16t, K=64; thread = 1o x 4t ----
    float a0 = 0.f, a1 = 0.f, a2 = 0.f, a3 = 0.f;
    #pragma unroll 8
    for (int k = 0; k < 64; k++) {
        float4 h = *reinterpret_cast<const float4*>(&Hs[k * 16 + tq * 4]);
        float w = Ws[og * 65 + k];
        a0 = fmaf(w, h.x, a0);
        a1 = fmaf(w, h.y, a1);
        a2 = fmaf(w, h.z, a2);
        a3 = fmaf(w, h.w, a3);
    }
    __syncthreads();   // Hs reads done; reuse as gate

    // ---- Phase A3: sigmoid -> gate tile [o_local][16 t] ----
    {
        float bb = b2[o0 + og];
        float4 g;
        g.x = 1.f / (1.f + __expf(-(a0 + bb)));
        g.y = 1.f / (1.f + __expf(-(a1 + bb)));
        g.z = 1.f / (1.f + __expf(-(a2 + bb)));
        g.w = 1.f / (1.f + __expf(-(a3 + bb)));
        *reinterpret_cast<float4*>(&Hs[og * 16 + tq * 4]) = g;
    }
    __syncthreads();

    // ---- Phase B: out = gate * x over [64 d-rows][256 cols] ----
    // Warp w: rows w*8..w*8+7; each row = 64 float4, 2 per lane.
    int warp = tid >> 5, lane = tid & 31;
    int c0 = t0 * CS;

    #pragma unroll
    for (int r = 0; r < 8; r++) {
        int o_local = warp * 8 + r;
        size_t rowbase = ((size_t)(b * D) + o0 + o_local) * T + c0;
        const float4* xr = reinterpret_cast<const float4*>(x + rowbase);
        float4*       orp = reinterpret_cast<float4*>(out + rowbase);

        float4 x0 = xr[lane];
        float4 x1 = xr[lane + 32];
        float g0 = Hs[o_local * 16 + (lane >> 2)];
        float g1 = Hs[o_local * 16 + ((lane + 32) >> 2)];

        float4 v0 = make_float4(x0.x * g0, x0.y * g0, x0.z * g0, x0.w * g0);
        float4 v1 = make_float4(x1.x * g1, x1.y * g1, x1.z * g1, x1.w * g1);
        __stcs(&orp[lane], v0);
        __stcs(&orp[lane + 32], v1);
    }
}

// ---------------------------------------------------------------------------
extern "C" void kernel_launch(void* const* d_in, const int* in_sizes, int n_in,
                              void* d_out, int out_size) {
    const float* x  = (const float*)d_in[0];
    const float* w1 = (const float*)d_in[1];
    const float* b1 = (const float*)d_in[2];
    const float* w2 = (const float*)d_in[3];
    const float* b2 = (const float*)d_in[4];
    float* out = (float*)d_out;

    pool_kernel<<<B * D, 512>>>(x);
    gemm1_kernel<<<dim3(8, 4, B), 256>>>(w1);
    gate_scale_kernel<<<dim3(32, 8, B), 256>>>(w2, b1, b2, x, out);
}

// round 13
// speedup vs baseline: 1.3041x; 1.0020x over previous
#include <cuda_runtime.h>

#define B  8
#define D  512
#define T  8192
#define CS 16
#define TC 512   // T / CS
#define DH 64    // D / 8

// Scratch (no cudaMalloc allowed)
__device__ float g_pooled[B * D * TC];          // 8 MiB
__device__ float g_hpart[4][B * DH * TC];       // 1 MiB per split-K slice

// ---------------------------------------------------------------------------
// Kernel 1: per (b,d) row — chunk sums of 16, inclusive scan, divide by count.
// Measured 23.7 us (~74% DRAM ceiling). Triggers PDL completion after store.
// ---------------------------------------------------------------------------
__global__ void pool_kernel(const float* __restrict__ x) {
    int row = blockIdx.x;                      // b*D + d
    const float4* xr = reinterpret_cast<const float4*>(x) + (size_t)row * (T / 4);
    int j = threadIdx.x;

    __shared__ float csum[TC];
    __shared__ float wsum[16];

    float4 f0 = xr[j];
    float4 f1 = xr[j + 512];
    float4 f2 = xr[j + 1024];
    float4 f3 = xr[j + 1536];

    float s0 = (f0.x + f0.y) + (f0.z + f0.w);
    float s1 = (f1.x + f1.y) + (f1.z + f1.w);
    float s2 = (f2.x + f2.y) + (f2.z + f2.w);
    float s3 = (f3.x + f3.y) + (f3.z + f3.w);

    s0 += __shfl_xor_sync(0xffffffffu, s0, 1);
    s0 += __shfl_xor_sync(0xffffffffu, s0, 2);
    s1 += __shfl_xor_sync(0xffffffffu, s1, 1);
    s1 += __shfl_xor_sync(0xffffffffu, s1, 2);
    s2 += __shfl_xor_sync(0xffffffffu, s2, 1);
    s2 += __shfl_xor_sync(0xffffffffu, s2, 2);
    s3 += __shfl_xor_sync(0xffffffffu, s3, 1);
    s3 += __shfl_xor_sync(0xffffffffu, s3, 2);

    if ((j & 3) == 0) {
        int c = j >> 2;
        csum[c +   0] = s0;
        csum[c + 128] = s1;
        csum[c + 256] = s2;
        csum[c + 384] = s3;
    }
    __syncthreads();

    int lane = j & 31, warp = j >> 5;
    float v = csum[j];
    #pragma unroll
    for (int off = 1; off < 32; off <<= 1) {
        float n = __shfl_up_sync(0xffffffffu, v, off);
        if (lane >= off) v += n;
    }
    if (lane == 31) wsum[warp] = v;
    __syncthreads();
    if (warp == 0) {
        float w = (lane < 16) ? wsum[lane] : 0.f;
        #pragma unroll
        for (int off = 1; off < 16; off <<= 1) {
            float n = __shfl_up_sync(0xffffffffu, w, off);
            if (lane >= off) w += n;
        }
        if (lane < 16) wsum[lane] = w;
    }
    __syncthreads();

    float prefix = (warp > 0) ? wsum[warp - 1] : 0.f;
    float total  = v + prefix;
    g_pooled[(size_t)row * TC + j] = total / (float)(CS * (j + 1));

    cudaTriggerProgrammaticLaunchCompletion();
}

// ---------------------------------------------------------------------------
// Kernel 2a: GEMM1 split-K partials. PDL: preloads w1 chunk 0 (16 KiB, no
// dependency) before the grid sync. grid (8, 4, B) = 256 CTAs.
// ---------------------------------------------------------------------------
__global__ void __launch_bounds__(256) gemm1_kernel(const float* __restrict__ w1) {
    __shared__ __align__(16) float Ps[64 * 64];      // [d][t] 16 KiB
    __shared__ __align__(16) float Ws[64 * 65 + 4];  // [o][d] padded

    int tid = threadIdx.x;
    int t0 = blockIdx.x * 64;
    int k0 = blockIdx.y * 128;
    int b  = blockIdx.z;
    int tq = tid & 15;          // t quad -> t = tq*4..tq*4+3
    int og = tid >> 4;          // 0..15  -> o = og*4..og*4+3

    float acc[4][4];
    #pragma unroll
    for (int o = 0; o < 4; o++)
        #pragma unroll
        for (int q = 0; q < 4; q++) acc[o][q] = 0.f;

    // Independent prologue: w1 chunk 0
    #pragma unroll
    for (int i = tid; i < 64 * 64; i += 256) {
        int o = i >> 6, d = i & 63;
        Ws[o * 65 + d] = w1[o * D + k0 + d];
    }

    cudaGridDependencySynchronize();

    for (int c = 0; c < 2; c++) {
        int kc = k0 + c * 64;
        if (c == 1) {
            #pragma unroll
            for (int i = tid; i < 64 * 64; i += 256) {
                int o = i >> 6, d = i & 63;
                Ws[o * 65 + d] = w1[o * D + kc + d];
            }
        }
        #pragma unroll
        for (int i = tid; i < 64 * 16; i += 256) {
            int d = i >> 4, t4 = i & 15;
            *reinterpret_cast<float4*>(&Ps[d * 64 + t4 * 4]) =
                *reinterpret_cast<const float4*>(
                    &g_pooled[((size_t)(b * D) + kc + d) * TC + t0 + t4 * 4]);
        }
        __syncthreads();

        #pragma unroll 8
        for (int dd = 0; dd < 64; dd++) {
            float4 p = *reinterpret_cast<const float4*>(&Ps[dd * 64 + tq * 4]);
            #pragma unroll
            for (int o = 0; o < 4; o++) {
                float w = Ws[(og * 4 + o) * 65 + dd];
                acc[o][0] = fmaf(w, p.x, acc[o][0]);
                acc[o][1] = fmaf(w, p.y, acc[o][1]);
                acc[o][2] = fmaf(w, p.z, acc[o][2]);
                acc[o][3] = fmaf(w, p.w, acc[o][3]);
            }
        }
        __syncthreads();
    }

    float* hp = g_hpart[blockIdx.y];
    #pragma unroll
    for (int o = 0; o < 4; o++) {
        float4 v = make_float4(acc[o][0], acc[o][1], acc[o][2], acc[o][3]);
        *reinterpret_cast<float4*>(
            &hp[((size_t)(b * DH) + og * 4 + o) * TC + t0 + tq * 4]) = v;
    }

    cudaTriggerProgrammaticLaunchCompletion();
}

// ---------------------------------------------------------------------------
// Kernel 2b (FUSED): gemm2 + sigmoid gate + out = gate * x.
// R12 winner config: grid (32, 8, 8) = 2048 CTAs (~1.7 waves), smem ~21 KiB.
// PDL: preloads W2 only (16 KiB, no dependency) before the grid sync —
// NO x prefetch (that caused R10's regression).
// ---------------------------------------------------------------------------
__global__ void __launch_bounds__(256) gate_scale_kernel(
        const float* __restrict__ w2,
        const float* __restrict__ b1,
        const float* __restrict__ b2,
        const float* __restrict__ x,
        float* __restrict__ out) {
    __shared__ __align__(16) float Hs[64 * 16];      // [k][t] then gate [o][t]
    __shared__ __align__(16) float Ws[64 * 65 + 4];  // [o][k] padded

    int tid = threadIdx.x;
    int t0 = blockIdx.x * 16;                 // pooled-chunk tile start
    int o0 = (7 - blockIdx.y) * 64;           // reversed d-tile
    int b  = (B - 1) - blockIdx.z;            // reversed batch
    int tq = tid & 3;                         // t quad: t = tq*4..+3
    int og = tid >> 2;                        // 0..63 -> one o row

    // Independent prologue: W2 (no dependency on gemm1)
    #pragma unroll
    for (int i = tid; i < 64 * 64; i += 256) {
        int o = i >> 6, k = i & 63;
        Ws[o * 65 + k] = w2[(o0 + o) * DH + k];
    }

    cudaGridDependencySynchronize();

    // ---- Phase A1: H = relu(sum hpart + b1)  (one float4 per thread) ----
    {
        int k = tid >> 2, t4 = tid & 3;
        size_t idx = ((size_t)(b * DH) + k) * TC + t0 + t4 * 4;
        float4 a0 = *reinterpret_cast<const float4*>(&g_hpart[0][idx]);
        float4 a1 = *reinterpret_cast<const float4*>(&g_hpart[1][idx]);
        float4 a2 = *reinterpret_cast<const float4*>(&g_hpart[2][idx]);
        float4 a3 = *reinterpret_cast<const float4*>(&g_hpart[3][idx]);
        float bb = b1[k];
        float4 hv;
        hv.x = fmaxf(a0.x + a1.x + a2.x + a3.x + bb, 0.f);
        hv.y = fmaxf(a0.y + a1.y + a2.y + a3.y + bb, 0.f);
        hv.z = fmaxf(a0.z + a1.z + a2.z + a3.z + bb, 0.f);
        hv.w = fmaxf(a0.w + a1.w + a2.w + a3.w + bb, 0.f);
        *reinterpret_cast<float4*>(&Hs[k * 16 + t4 * 4]) = hv;
    }
    __syncthreads();

    // ---- Phase A2: GEMM 64o x 16t, K=64; thread = 1o x 4t ----
    float a0 = 0.f, a1 = 0.f, a2 = 0.f, a3 = 0.f;
    #pragma unroll 8
    for (int k = 0; k < 64; k++) {
        float4 h = *reinterpret_cast<const float4*>(&Hs[k * 16 + tq * 4]);
        float w = Ws[og * 65 + k];
        a0 = fmaf(w, h.x, a0);
        a1 = fmaf(w, h.y, a1);
        a2 = fmaf(w, h.z, a2);
        a3 = fmaf(w, h.w, a3);
    }
    __syncthreads();   // Hs reads done; reuse as gate

    // ---- Phase A3: sigmoid -> gate tile [o_local][16 t] ----
    {
        float bb = b2[o0 + og];
        float4 g;
        g.x = 1.f / (1.f + __expf(-(a0 + bb)));
        g.y = 1.f / (1.f + __expf(-(a1 + bb)));
        g.z = 1.f / (1.f + __expf(-(a2 + bb)));
        g.w = 1.f / (1.f + __expf(-(a3 + bb)));
        *reinterpret_cast<float4*>(&Hs[og * 16 + tq * 4]) = g;
    }
    __syncthreads();

    // ---- Phase B: out = gate * x over [64 d-rows][256 cols] ----
    int warp = tid >> 5, lane = tid & 31;
    int c0 = t0 * CS;

    #pragma unroll
    for (int r = 0; r < 8; r++) {
        int o_local = warp * 8 + r;
        size_t rowbase = ((size_t)(b * D) + o0 + o_local) * T + c0;
        const float4* xr = reinterpret_cast<const float4*>(x + rowbase);
        float4*       orp = reinterpret_cast<float4*>(out + rowbase);

        float4 x0 = xr[lane];
        float4 x1 = xr[lane + 32];
        float g0 = Hs[o_local * 16 + (lane >> 2)];
        float g1 = Hs[o_local * 16 + ((lane + 32) >> 2)];

        float4 v0 = make_float4(x0.x * g0, x0.y * g0, x0.z * g0, x0.w * g0);
        float4 v1 = make_float4(x1.x * g1, x1.y * g1, x1.z * g1, x1.w * g1);
        __stcs(&orp[lane], v0);
        __stcs(&orp[lane + 32], v1);
    }
}

// ---------------------------------------------------------------------------
extern "C" void kernel_launch(void* const* d_in, const int* in_sizes, int n_in,
                              void* d_out, int out_size) {
    const float* x  = (const float*)d_in[0];
    const float* w1 = (const float*)d_in[1];
    const float* b1 = (const float*)d_in[2];
    const float* w2 = (const float*)d_in[3];
    const float* b2 = (const float*)d_in[4];
    float* out = (float*)d_out;

    pool_kernel<<<B * D, 512>>>(x);

    cudaLaunchAttribute attrs[1];
    attrs[0].id = cudaLaunchAttributeProgrammaticStreamSerialization;
    attrs[0].val.programmaticStreamSerializationAllowed = 1;

    {
        cudaLaunchConfig_t cfg = {};
        cfg.gridDim  = dim3(8, 4, B);
        cfg.blockDim = dim3(256, 1, 1);
        cfg.attrs = attrs;
        cfg.numAttrs = 1;
        cfg.stream = 0;
        cudaLaunchKernelEx(&cfg, gemm1_kernel, w1);
    }
    {
        cudaLaunchConfig_t cfg = {};
        cfg.gridDim  = dim3(32, 8, B);
        cfg.blockDim = dim3(256, 1, 1);
        cfg.attrs = attrs;
        cfg.numAttrs = 1;
        cfg.stream = 0;
        cudaLaunchKernelEx(&cfg, gate_scale_kernel, w2, b1, b2, x, out);
    }
}